// round 15
// baseline (speedup 1.0000x reference)
#include <cuda_runtime.h>
#include <cuda_fp16.h>
#include <cstdint>

#define NN 50000
#define NPAD 50176          // 392 * 128
#define DIM 512
#define NCOL 1024
#define BM 128
#define BN 128
#define BK 64               // fp16 per k-chunk = 128 bytes per row
#define CHUNKS 8            // DIM / BK
#define STAGES 3
#define STAGE_BYTES 32768   // A 16KB + B 16KB
#define SMEM_TOTAL (STAGES * STAGE_BYTES)

typedef unsigned long long ull;

// ---------------- static device scratch (no allocation) ----------------
__device__ __align__(16) __half g_Ah[(size_t)NPAD * DIM];    // 51 MB  fp16 A
__device__ __align__(16) __half g_B1p[NCOL * DIM];           // 1 MB  Bh layer1
__device__ __align__(16) __half g_B2p[NCOL * DIM];           // 1 MB  Bh layer2
__device__ __align__(16) __half g_Ch[(size_t)NPAD * NCOL];   // 102 MB  fp16 C
__device__ float g_part[2 * NN];

// ---------------- PTX helpers ----------------
__device__ __forceinline__ uint32_t smem_u32(const void* p) {
    uint32_t a;
    asm("{ .reg .u64 t; cvta.to.shared.u64 t, %1; cvt.u32.u64 %0, t; }" : "=r"(a) : "l"(p));
    return a;
}
#define CP16(dst, src) asm volatile("cp.async.cg.shared.global [%0], [%1], 16;" :: "r"(dst), "l"(src))
#define CP_COMMIT()    asm volatile("cp.async.commit_group;" ::: "memory")
#define CP_WAIT(n)     asm volatile("cp.async.wait_group %0;" :: "n"(n) : "memory")

#define LDSM_X4(r0, r1, r2, r3, a) \
    asm volatile("ldmatrix.sync.aligned.m8n8.x4.shared.b16 {%0,%1,%2,%3}, [%4];" \
        : "=r"(r0), "=r"(r1), "=r"(r2), "=r"(r3) : "r"(a))

#define MMA16816(c, a, b) \
    asm volatile("mma.sync.aligned.m16n8k16.row.col.f32.f16.f16.f32 " \
        "{%0,%1,%2,%3}, {%4,%5,%6,%7}, {%8,%9}, {%0,%1,%2,%3};" \
        : "+f"((c)[0]), "+f"((c)[1]), "+f"((c)[2]), "+f"((c)[3]) \
        : "r"((a)[0]), "r"((a)[1]), "r"((a)[2]), "r"((a)[3]), "r"((b)[0]), "r"((b)[1]))

// ---------------- fused prep: convert x -> fp16 (blocks 0..NPAD/4-1),
//                  pack W1/W2 -> fp16 (blocks NPAD/4..NPAD/4+511) ----------------
#define CONV_BLOCKS (NPAD / 4)
__global__ void prep_kernel(const float* __restrict__ x,
                            const float* __restrict__ W1,
                            const float* __restrict__ W2) {
    int b = blockIdx.x;
    int tid = threadIdx.x;
    if (b < CONV_BLOCKS) {
        int i = b * 4 + (tid >> 6);
        int j = (tid & 63) * 8;
        __half* row = g_Ah + (size_t)i * DIM;
        if (i >= NN) { *(uint4*)(row + j) = make_uint4(0, 0, 0, 0); return; }
        float4 a = *(const float4*)(x + (size_t)i * DIM + j);
        float4 c = *(const float4*)(x + (size_t)i * DIM + j + 4);
        __half h[8] = { __float2half_rn(a.x), __float2half_rn(a.y),
                        __float2half_rn(a.z), __float2half_rn(a.w),
                        __float2half_rn(c.x), __float2half_rn(c.y),
                        __float2half_rn(c.z), __float2half_rn(c.w) };
        *(uint4*)(row + j) = *(uint4*)h;
    } else {
        int e = ((b - CONV_BLOCKS) * 256 + tid) * 4;       // 4 consecutive elems, same n
        int n = e >> 9, k = e & 511;
        int src = (n < DIM) ? (n * NCOL + k) : ((n - DIM) * NCOL + DIM + k);
        float4 w1 = *(const float4*)(W1 + src);
        float4 w2 = *(const float4*)(W2 + src);
        __half h1[4] = { __float2half_rn(w1.x), __float2half_rn(w1.y),
                         __float2half_rn(w1.z), __float2half_rn(w1.w) };
        __half h2[4] = { __float2half_rn(w2.x), __float2half_rn(w2.y),
                         __float2half_rn(w2.z), __float2half_rn(w2.w) };
        *(ull*)(g_B1p + e) = *(ull*)h1;
        *(ull*)(g_B2p + e) = *(ull*)h2;
    }
}

// ---------------- fp16 HMMA GEMM: g_Ch[M,1024] = A[M,512] @ B^T ----------------
// CTA 128x128x64, warp tile 64x32, 3-stage cp.async pipeline, 2 CTAs/SM.
__global__ __launch_bounds__(256, 2) void gemm_kernel(int layer) {
    extern __shared__ __align__(1024) char smem[];
    const uint32_t sbase = smem_u32(smem);
    const int tid = threadIdx.x;
    const int wid = tid >> 5;
    const int lane = tid & 31;
    const int wm = wid & 1;           // 2 warps along M
    const int wn = wid >> 1;          // 4 warps along N
    const __half* __restrict__ Bp = layer ? g_B2p : g_B1p;
    const size_t mBase = (size_t)blockIdx.y * BM;
    const int nBase = blockIdx.x * BN;

    const char* gA0 = (const char*)g_Ah + mBase * (DIM * 2);
    const char* gB0 = (const char*)Bp + (size_t)nBase * (DIM * 2);

    auto load_chunk = [&](int kc, int s) {
        uint32_t sA = sbase + s * STAGE_BYTES;
        uint32_t sB = sA + 16384;
        const char* gA = gA0 + kc * 128;
        const char* gB = gB0 + kc * 128;
        #pragma unroll
        for (int i = 0; i < 4; i++) {
            int u = tid + i * 256;            // 0..1023
            int r = u >> 3, c = u & 7;
            uint32_t sw = (uint32_t)(r * 128 + (((c ^ (r & 7))) << 4));
            CP16(sA + sw, gA + (size_t)r * 1024 + c * 16);
            CP16(sB + sw, gB + (size_t)r * 1024 + c * 16);
        }
    };

    float acc[4][4][4];
    #pragma unroll
    for (int i = 0; i < 4; i++)
        #pragma unroll
        for (int j = 0; j < 4; j++)
            #pragma unroll
            for (int q = 0; q < 4; q++) acc[i][j][q] = 0.f;

    load_chunk(0, 0); CP_COMMIT();
    load_chunk(1, 1); CP_COMMIT();

    const int lrow = lane & 15;       // row within 16
    const int lhalf = lane >> 4;      // k-half

    #pragma unroll
    for (int kc = 0; kc < CHUNKS; kc++) {
        CP_WAIT(1);                   // chunk kc resident
        __syncthreads();

        uint32_t sA = sbase + (kc % STAGES) * STAGE_BYTES;
        uint32_t sB = sA + 16384;

        #pragma unroll
        for (int ks = 0; ks < 4; ks++) {
            uint32_t af[4][4], bf[4][2];
            #pragma unroll
            for (int am = 0; am < 4; am++) {
                int row = wm * 64 + am * 16 + lrow;
                int grp = ks * 2 + lhalf;
                uint32_t addr = sA + row * 128 + (((grp ^ (row & 7))) << 4);
                LDSM_X4(af[am][0], af[am][1], af[am][2], af[am][3], addr);
            }
            #pragma unroll
            for (int p = 0; p < 2; p++) {
                int row = wn * 32 + p * 16 + lrow;
                int grp = ks * 2 + lhalf;
                uint32_t addr = sB + row * 128 + (((grp ^ (row & 7))) << 4);
                uint32_t r0, r1, r2, r3;
                LDSM_X4(r0, r1, r2, r3, addr);
                bf[p * 2 + 0][0] = r0; bf[p * 2 + 0][1] = r2;
                bf[p * 2 + 1][0] = r1; bf[p * 2 + 1][1] = r3;
            }
            #pragma unroll
            for (int am = 0; am < 4; am++)
                #pragma unroll
                for (int bn = 0; bn < 4; bn++)
                    MMA16816(acc[am][bn], af[am], bf[bn]);
        }
        if (kc + 2 < CHUNKS) load_chunk(kc + 2, (kc + 2) % STAGES);
        CP_COMMIT();
    }

    // epilogue: fp16 store. c frag m16n8 -> (row = l>>2 [+8], col = (l&3)*2)
    const int crow = lane >> 2;
    const int ccol = (lane & 3) * 2;
    #pragma unroll
    for (int am = 0; am < 4; am++) {
        size_t r0 = mBase + wm * 64 + am * 16 + crow;
        #pragma unroll
        for (int bn = 0; bn < 4; bn++) {
            int c0 = nBase + wn * 32 + bn * 8 + ccol;
            __half2* p0 = (__half2*)(g_Ch + r0 * NCOL + c0);
            __half2* p1 = (__half2*)(g_Ch + (r0 + 8) * NCOL + c0);
            *p0 = __floats2half2_rn(acc[am][bn][0], acc[am][bn][1]);
            *p1 = __floats2half2_rn(acc[am][bn][2], acc[am][bn][3]);
        }
    }
}

// ---------------- layer-1 combine -> fp16: A <- relu(Y + 0.5*(Z0+Z1)) ----------------
__device__ __forceinline__ float2 h2f(uint32_t u) { return __half22float2(*(__half2*)&u); }

// 4 rows per 256-thread block; 64 threads per row, 8 halves each (16B loads).
__global__ void combine1_kernel(const int* __restrict__ neighs) {
    int i = blockIdx.x * 4 + (threadIdx.x >> 6);
    int j = (threadIdx.x & 63) * 8;
    __half* row = g_Ah + (size_t)i * DIM;
    if (i >= NN) { *(uint4*)(row + j) = make_uint4(0, 0, 0, 0); return; }
    int n0 = neighs[2 * i], n1 = neighs[2 * i + 1];
    uint4 ys = *(const uint4*)(g_Ch + (size_t)i  * NCOL + j);
    uint4 z0 = *(const uint4*)(g_Ch + (size_t)n0 * NCOL + DIM + j);
    uint4 z1 = *(const uint4*)(g_Ch + (size_t)n1 * NCOL + DIM + j);
    const uint32_t* yp = &ys.x;
    const uint32_t* p0 = &z0.x;
    const uint32_t* p1 = &z1.x;
    __half h[8];
    #pragma unroll
    for (int q = 0; q < 4; q++) {
        float2 s = h2f(yp[q]), a0 = h2f(p0[q]), a1 = h2f(p1[q]);
        h[q * 2 + 0] = __float2half_rn(fmaxf(fmaf(0.5f, a0.x + a1.x, s.x), 0.f));
        h[q * 2 + 1] = __float2half_rn(fmaxf(fmaf(0.5f, a0.y + a1.y, s.y), 0.f));
    }
    *(uint4*)(row + j) = *(uint4*)h;
}

// ---------------- layer-2 combine fused with FC-head partial dots ----------------
// 1 warp per row, 8 rows per 256-thread block. Each thread: 16 halves
// (2 x uint4 per source stream), all loads issued before compute (MLP 6).
// Shuffle-only reduction; no smem, no block barrier.
__global__ void combine2_kernel(const int* __restrict__ neighs,
                                const float* __restrict__ fcw,
                                float* __restrict__ out) {
    int tid = threadIdx.x;
    int lane = tid & 31;
    int i = blockIdx.x * 8 + (tid >> 5);
    int j = lane * 16;
    int n0 = neighs[2 * i], n1 = neighs[2 * i + 1];
    const uint4* ysp = (const uint4*)(g_Ch + (size_t)i  * NCOL + j);
    const uint4* z0p = (const uint4*)(g_Ch + (size_t)n0 * NCOL + DIM + j);
    const uint4* z1p = (const uint4*)(g_Ch + (size_t)n1 * NCOL + DIM + j);
    uint4 ys0 = ysp[0], ys1 = ysp[1];
    uint4 za0 = z0p[0], za1 = z0p[1];
    uint4 zb0 = z1p[0], zb1 = z1p[1];

    size_t idx = (size_t)i * DIM + j;
    uint32_t yw[8] = { ys0.x, ys0.y, ys0.z, ys0.w, ys1.x, ys1.y, ys1.z, ys1.w };
    uint32_t aw[8] = { za0.x, za0.y, za0.z, za0.w, za1.x, za1.y, za1.z, za1.w };
    uint32_t bw[8] = { zb0.x, zb0.y, zb0.z, zb0.w, zb1.x, zb1.y, zb1.z, zb1.w };

    float o[16];
    #pragma unroll
    for (int q = 0; q < 8; q++) {
        float2 s = h2f(yw[q]), a0 = h2f(aw[q]), a1 = h2f(bw[q]);
        o[q * 2 + 0] = fmaxf(fmaf(0.5f, a0.x + a1.x, s.x), 0.f);
        o[q * 2 + 1] = fmaxf(fmaf(0.5f, a0.y + a1.y, s.y), 0.f);
    }
    #pragma unroll
    for (int q = 0; q < 4; q++)
        *(float4*)(out + idx + q * 4) = make_float4(o[q * 4], o[q * 4 + 1],
                                                    o[q * 4 + 2], o[q * 4 + 3]);

    float p0s = 0.f, p1s = 0.f;
    #pragma unroll
    for (int q = 0; q < 4; q++) {
        float4 w0 = *(const float4*)(fcw + idx + q * 4);
        float4 w1 = *(const float4*)(fcw + (size_t)NN * DIM + idx + q * 4);
        const float* ov = o + q * 4;
        p0s += ov[0] * w0.x + ov[1] * w0.y + ov[2] * w0.z + ov[3] * w0.w;
        p1s += ov[0] * w1.x + ov[1] * w1.y + ov[2] * w1.z + ov[3] * w1.w;
    }

    #pragma unroll
    for (int st = 16; st > 0; st >>= 1) {
        p0s += __shfl_down_sync(0xFFFFFFFF, p0s, st);
        p1s += __shfl_down_sync(0xFFFFFFFF, p1s, st);
    }
    if (lane == 0) { g_part[i] = p0s; g_part[NN + i] = p1s; }
}

// ---------------- final: deterministic reduce + bias + log_softmax ----------------
__global__ void final_kernel(const float* __restrict__ fcb, float* __restrict__ out2) {
    __shared__ float s0[1024], s1[1024];
    int tid = threadIdx.x;
    float a = 0.f, b = 0.f;
    for (int i = tid; i < NN; i += 1024) { a += g_part[i]; b += g_part[NN + i]; }
    s0[tid] = a; s1[tid] = b;
    __syncthreads();
    #pragma unroll
    for (int st = 512; st > 0; st >>= 1) {
        if (tid < st) { s0[tid] += s0[tid + st]; s1[tid] += s1[tid + st]; }
        __syncthreads();
    }
    if (tid == 0) {
        float l0 = s0[0] + fcb[0];
        float l1 = s1[0] + fcb[1];
        float m = fmaxf(l0, l1);
        float lse = m + logf(expf(l0 - m) + expf(l1 - m));
        out2[0] = l0 - lse;
        out2[1] = l1 - lse;
    }
}

// ---------------- launch ----------------
extern "C" void kernel_launch(void* const* d_in, const int* in_sizes, int n_in,
                              void* d_out, int out_size) {
    const float* x   = (const float*)d_in[0];
    const int*   nb1 = (const int*)  d_in[1];
    const int*   nb2 = (const int*)  d_in[2];
    const float* W1  = (const float*)d_in[3];
    const float* W2  = (const float*)d_in[4];
    const float* fcw = (const float*)d_in[5];
    const float* fcb = (const float*)d_in[6];
    float* out = (float*)d_out;

    cudaFuncSetAttribute(gemm_kernel, cudaFuncAttributeMaxDynamicSharedMemorySize, SMEM_TOTAL);

    prep_kernel<<<CONV_BLOCKS + (NCOL * DIM) / 1024, 256>>>(x, W1, W2);

    dim3 grid(NCOL / BN, NPAD / BM);                       // (8, 392)
    gemm_kernel<<<grid, 256, SMEM_TOTAL>>>(0);             // layer 1 -> g_Ch
    combine1_kernel<<<NPAD / 4, 256>>>(nb1);               // -> g_Ah (fp16)
    gemm_kernel<<<grid, 256, SMEM_TOTAL>>>(1);             // layer 2 -> g_Ch
    combine2_kernel<<<NN / 8, 256>>>(nb2, fcw, out);       // flat -> d_out, FC partials
    final_kernel<<<1, 1024>>>(fcb, out + (size_t)(out_size - 2));
}

// round 16
// speedup vs baseline: 1.0017x; 1.0017x over previous
#include <cuda_runtime.h>
#include <cuda_fp16.h>
#include <cstdint>

#define NN 50000
#define NPAD 50176          // 392 * 128
#define DIM 512
#define NCOL 1024
#define BM 128
#define BN 128
#define BK 64               // fp16 per k-chunk = 128 bytes per row
#define CHUNKS 8            // DIM / BK
#define STAGES 3
#define STAGE_BYTES 32768   // A 16KB + B 16KB
#define SMEM_TOTAL (STAGES * STAGE_BYTES)
#define FW_E ((size_t)2 * NN * DIM)      // 51.2M fcw elements

typedef unsigned long long ull;

// ---------------- static device scratch (no allocation) ----------------
__device__ __align__(16) __half g_Ah[(size_t)NPAD * DIM];    // 51 MB  fp16 A
__device__ __align__(16) __half g_B1p[NCOL * DIM];           // 1 MB  Bh layer1
__device__ __align__(16) __half g_B2p[NCOL * DIM];           // 1 MB  Bh layer2
__device__ __align__(16) __half g_Ch[(size_t)NPAD * NCOL];   // 102 MB  fp16 C
__device__ __align__(16) __half g_fw16[FW_E];                // 102 MB  fp16 fcw
__device__ float g_part[2 * NN];

// ---------------- PTX helpers ----------------
__device__ __forceinline__ uint32_t smem_u32(const void* p) {
    uint32_t a;
    asm("{ .reg .u64 t; cvta.to.shared.u64 t, %1; cvt.u32.u64 %0, t; }" : "=r"(a) : "l"(p));
    return a;
}
#define CP16(dst, src) asm volatile("cp.async.cg.shared.global [%0], [%1], 16;" :: "r"(dst), "l"(src))
#define CP_COMMIT()    asm volatile("cp.async.commit_group;" ::: "memory")
#define CP_WAIT(n)     asm volatile("cp.async.wait_group %0;" :: "n"(n) : "memory")

#define LDSM_X4(r0, r1, r2, r3, a) \
    asm volatile("ldmatrix.sync.aligned.m8n8.x4.shared.b16 {%0,%1,%2,%3}, [%4];" \
        : "=r"(r0), "=r"(r1), "=r"(r2), "=r"(r3) : "r"(a))

#define MMA16816(c, a, b) \
    asm volatile("mma.sync.aligned.m16n8k16.row.col.f32.f16.f16.f32 " \
        "{%0,%1,%2,%3}, {%4,%5,%6,%7}, {%8,%9}, {%0,%1,%2,%3};" \
        : "+f"((c)[0]), "+f"((c)[1]), "+f"((c)[2]), "+f"((c)[3]) \
        : "r"((a)[0]), "r"((a)[1]), "r"((a)[2]), "r"((a)[3]), "r"((b)[0]), "r"((b)[1]))

__device__ __forceinline__ float2 h2f(uint32_t u) { return __half22float2(*(__half2*)&u); }

// ---------------- fused prep: convert x -> fp16 + pack W1/W2 -> fp16 ----------------
#define CONV_BLOCKS (NPAD / 4)
__global__ void prep_kernel(const float* __restrict__ x,
                            const float* __restrict__ W1,
                            const float* __restrict__ W2) {
    int b = blockIdx.x;
    int tid = threadIdx.x;
    if (b < CONV_BLOCKS) {
        int i = b * 4 + (tid >> 6);
        int j = (tid & 63) * 8;
        __half* row = g_Ah + (size_t)i * DIM;
        if (i >= NN) { *(uint4*)(row + j) = make_uint4(0, 0, 0, 0); return; }
        float4 a = *(const float4*)(x + (size_t)i * DIM + j);
        float4 c = *(const float4*)(x + (size_t)i * DIM + j + 4);
        __half h[8] = { __float2half_rn(a.x), __float2half_rn(a.y),
                        __float2half_rn(a.z), __float2half_rn(a.w),
                        __float2half_rn(c.x), __float2half_rn(c.y),
                        __float2half_rn(c.z), __float2half_rn(c.w) };
        *(uint4*)(row + j) = *(uint4*)h;
    } else {
        int e = ((b - CONV_BLOCKS) * 256 + tid) * 4;       // 4 consecutive elems, same n
        int n = e >> 9, k = e & 511;
        int src = (n < DIM) ? (n * NCOL + k) : ((n - DIM) * NCOL + DIM + k);
        float4 w1 = *(const float4*)(W1 + src);
        float4 w2 = *(const float4*)(W2 + src);
        __half h1[4] = { __float2half_rn(w1.x), __float2half_rn(w1.y),
                         __float2half_rn(w1.z), __float2half_rn(w1.w) };
        __half h2[4] = { __float2half_rn(w2.x), __float2half_rn(w2.y),
                         __float2half_rn(w2.z), __float2half_rn(w2.w) };
        *(ull*)(g_B1p + e) = *(ull*)h1;
        *(ull*)(g_B2p + e) = *(ull*)h2;
    }
}

// ---------------- fp16 HMMA GEMM: g_Ch[M,1024] = A[M,512] @ B^T ----------------
// CTA 128x128x64, warp tile 64x32, 3-stage cp.async pipeline, 2 CTAs/SM.
// Layer-0 launch uses grid.x == 9: the blockIdx.x==8 CTAs are pure streaming
// converters (fcw fp32 -> fp16) riding the idle DRAM under GEMM compute.
__global__ __launch_bounds__(256, 2) void gemm_kernel(int layer,
                                                      const float* __restrict__ fcw) {
    if (blockIdx.x == 8) {
        // fcw converter: 392 blocks x 256 threads, 8 elems/thread/step
        size_t base = ((size_t)blockIdx.y * 256 + threadIdx.x) * 8;
        const size_t stride = (size_t)392 * 256 * 8;
        for (size_t e = base; e < FW_E; e += stride) {
            float4 a = *(const float4*)(fcw + e);
            float4 b = *(const float4*)(fcw + e + 4);
            __half h[8] = { __float2half_rn(a.x), __float2half_rn(a.y),
                            __float2half_rn(a.z), __float2half_rn(a.w),
                            __float2half_rn(b.x), __float2half_rn(b.y),
                            __float2half_rn(b.z), __float2half_rn(b.w) };
            *(uint4*)(g_fw16 + e) = *(uint4*)h;
        }
        return;
    }

    extern __shared__ __align__(1024) char smem[];
    const uint32_t sbase = smem_u32(smem);
    const int tid = threadIdx.x;
    const int wid = tid >> 5;
    const int lane = tid & 31;
    const int wm = wid & 1;           // 2 warps along M
    const int wn = wid >> 1;          // 4 warps along N
    const __half* __restrict__ Bp = layer ? g_B2p : g_B1p;
    const size_t mBase = (size_t)blockIdx.y * BM;
    const int nBase = blockIdx.x * BN;

    const char* gA0 = (const char*)g_Ah + mBase * (DIM * 2);
    const char* gB0 = (const char*)Bp + (size_t)nBase * (DIM * 2);

    auto load_chunk = [&](int kc, int s) {
        uint32_t sA = sbase + s * STAGE_BYTES;
        uint32_t sB = sA + 16384;
        const char* gA = gA0 + kc * 128;
        const char* gB = gB0 + kc * 128;
        #pragma unroll
        for (int i = 0; i < 4; i++) {
            int u = tid + i * 256;            // 0..1023
            int r = u >> 3, c = u & 7;
            uint32_t sw = (uint32_t)(r * 128 + (((c ^ (r & 7))) << 4));
            CP16(sA + sw, gA + (size_t)r * 1024 + c * 16);
            CP16(sB + sw, gB + (size_t)r * 1024 + c * 16);
        }
    };

    float acc[4][4][4];
    #pragma unroll
    for (int i = 0; i < 4; i++)
        #pragma unroll
        for (int j = 0; j < 4; j++)
            #pragma unroll
            for (int q = 0; q < 4; q++) acc[i][j][q] = 0.f;

    load_chunk(0, 0); CP_COMMIT();
    load_chunk(1, 1); CP_COMMIT();

    const int lrow = lane & 15;       // row within 16
    const int lhalf = lane >> 4;      // k-half

    #pragma unroll
    for (int kc = 0; kc < CHUNKS; kc++) {
        CP_WAIT(1);                   // chunk kc resident
        __syncthreads();

        uint32_t sA = sbase + (kc % STAGES) * STAGE_BYTES;
        uint32_t sB = sA + 16384;

        #pragma unroll
        for (int ks = 0; ks < 4; ks++) {
            uint32_t af[4][4], bf[4][2];
            #pragma unroll
            for (int am = 0; am < 4; am++) {
                int row = wm * 64 + am * 16 + lrow;
                int grp = ks * 2 + lhalf;
                uint32_t addr = sA + row * 128 + (((grp ^ (row & 7))) << 4);
                LDSM_X4(af[am][0], af[am][1], af[am][2], af[am][3], addr);
            }
            #pragma unroll
            for (int p = 0; p < 2; p++) {
                int row = wn * 32 + p * 16 + lrow;
                int grp = ks * 2 + lhalf;
                uint32_t addr = sB + row * 128 + (((grp ^ (row & 7))) << 4);
                uint32_t r0, r1, r2, r3;
                LDSM_X4(r0, r1, r2, r3, addr);
                bf[p * 2 + 0][0] = r0; bf[p * 2 + 0][1] = r2;
                bf[p * 2 + 1][0] = r1; bf[p * 2 + 1][1] = r3;
            }
            #pragma unroll
            for (int am = 0; am < 4; am++)
                #pragma unroll
                for (int bn = 0; bn < 4; bn++)
                    MMA16816(acc[am][bn], af[am], bf[bn]);
        }
        if (kc + 2 < CHUNKS) load_chunk(kc + 2, (kc + 2) % STAGES);
        CP_COMMIT();
    }

    // epilogue: fp16 store. c frag m16n8 -> (row = l>>2 [+8], col = (l&3)*2)
    const int crow = lane >> 2;
    const int ccol = (lane & 3) * 2;
    #pragma unroll
    for (int am = 0; am < 4; am++) {
        size_t r0 = mBase + wm * 64 + am * 16 + crow;
        #pragma unroll
        for (int bn = 0; bn < 4; bn++) {
            int c0 = nBase + wn * 32 + bn * 8 + ccol;
            __half2* p0 = (__half2*)(g_Ch + r0 * NCOL + c0);
            __half2* p1 = (__half2*)(g_Ch + (r0 + 8) * NCOL + c0);
            *p0 = __floats2half2_rn(acc[am][bn][0], acc[am][bn][1]);
            *p1 = __floats2half2_rn(acc[am][bn][2], acc[am][bn][3]);
        }
    }
}

// ---------------- layer-1 combine -> fp16: A <- relu(Y + 0.5*(Z0+Z1)) ----------------
// 4 rows per 256-thread block; 64 threads per row, 8 halves each (16B loads).
__global__ void combine1_kernel(const int* __restrict__ neighs) {
    int i = blockIdx.x * 4 + (threadIdx.x >> 6);
    int j = (threadIdx.x & 63) * 8;
    __half* row = g_Ah + (size_t)i * DIM;
    if (i >= NN) { *(uint4*)(row + j) = make_uint4(0, 0, 0, 0); return; }
    int n0 = neighs[2 * i], n1 = neighs[2 * i + 1];
    uint4 ys = *(const uint4*)(g_Ch + (size_t)i  * NCOL + j);
    uint4 z0 = *(const uint4*)(g_Ch + (size_t)n0 * NCOL + DIM + j);
    uint4 z1 = *(const uint4*)(g_Ch + (size_t)n1 * NCOL + DIM + j);
    const uint32_t* yp = &ys.x;
    const uint32_t* p0 = &z0.x;
    const uint32_t* p1 = &z1.x;
    __half h[8];
    #pragma unroll
    for (int q = 0; q < 4; q++) {
        float2 s = h2f(yp[q]), a0 = h2f(p0[q]), a1 = h2f(p1[q]);
        h[q * 2 + 0] = __float2half_rn(fmaxf(fmaf(0.5f, a0.x + a1.x, s.x), 0.f));
        h[q * 2 + 1] = __float2half_rn(fmaxf(fmaf(0.5f, a0.y + a1.y, s.y), 0.f));
    }
    *(uint4*)(row + j) = *(uint4*)h;
}

// ---------------- layer-2 combine fused with FC-head partial dots ----------------
// 8 rows per 512-thread block; 2 warps per row; fp16 fcw (g_fw16).
__global__ void combine2_kernel(const int* __restrict__ neighs,
                                float* __restrict__ out) {
    int tid = threadIdx.x;
    int i = blockIdx.x * 8 + (tid >> 6);
    int j = (tid & 63) * 8;
    int n0 = neighs[2 * i], n1 = neighs[2 * i + 1];
    uint4 ys = *(const uint4*)(g_Ch + (size_t)i  * NCOL + j);
    uint4 z0 = *(const uint4*)(g_Ch + (size_t)n0 * NCOL + DIM + j);
    uint4 z1 = *(const uint4*)(g_Ch + (size_t)n1 * NCOL + DIM + j);
    size_t idx = (size_t)i * DIM + j;
    uint4 w0 = *(const uint4*)(g_fw16 + idx);
    uint4 w1 = *(const uint4*)(g_fw16 + (size_t)NN * DIM + idx);
    const uint32_t* yp = &ys.x;
    const uint32_t* p0 = &z0.x;
    const uint32_t* p1 = &z1.x;
    const uint32_t* w0p = &w0.x;
    const uint32_t* w1p = &w1.x;
    float o[8];
    #pragma unroll
    for (int q = 0; q < 4; q++) {
        float2 s = h2f(yp[q]), a0 = h2f(p0[q]), a1 = h2f(p1[q]);
        o[q * 2 + 0] = fmaxf(fmaf(0.5f, a0.x + a1.x, s.x), 0.f);
        o[q * 2 + 1] = fmaxf(fmaf(0.5f, a0.y + a1.y, s.y), 0.f);
    }
    *(float4*)(out + idx) = make_float4(o[0], o[1], o[2], o[3]);
    *(float4*)(out + idx + 4) = make_float4(o[4], o[5], o[6], o[7]);

    float p0s = 0.f, p1s = 0.f;
    #pragma unroll
    for (int q = 0; q < 4; q++) {
        float2 wa = h2f(w0p[q]), wb = h2f(w1p[q]);
        p0s = fmaf(o[q * 2], wa.x, fmaf(o[q * 2 + 1], wa.y, p0s));
        p1s = fmaf(o[q * 2], wb.x, fmaf(o[q * 2 + 1], wb.y, p1s));
    }

    // warp shuffle reduce (deterministic), then pair-combine the 2 warps per row
    #pragma unroll
    for (int st = 16; st > 0; st >>= 1) {
        p0s += __shfl_down_sync(0xFFFFFFFF, p0s, st);
        p1s += __shfl_down_sync(0xFFFFFFFF, p1s, st);
    }
    __shared__ float s0[16], s1[16];
    int w = tid >> 5;
    if ((tid & 31) == 0) { s0[w] = p0s; s1[w] = p1s; }
    __syncthreads();
    if ((tid & 63) == 0) {
        g_part[i]      = s0[w] + s0[w + 1];
        g_part[NN + i] = s1[w] + s1[w + 1];
    }
}

// ---------------- final: deterministic reduce + bias + log_softmax ----------------
__global__ void final_kernel(const float* __restrict__ fcb, float* __restrict__ out2) {
    __shared__ float s0[256], s1[256];
    int tid = threadIdx.x;
    float a = 0.f, b = 0.f;
    for (int i = tid; i < NN; i += 256) { a += g_part[i]; b += g_part[NN + i]; }
    s0[tid] = a; s1[tid] = b;
    __syncthreads();
    #pragma unroll
    for (int st = 128; st > 0; st >>= 1) {
        if (tid < st) { s0[tid] += s0[tid + st]; s1[tid] += s1[tid + st]; }
        __syncthreads();
    }
    if (tid == 0) {
        float l0 = s0[0] + fcb[0];
        float l1 = s1[0] + fcb[1];
        float m = fmaxf(l0, l1);
        float lse = m + logf(expf(l0 - m) + expf(l1 - m));
        out2[0] = l0 - lse;
        out2[1] = l1 - lse;
    }
}

// ---------------- launch ----------------
extern "C" void kernel_launch(void* const* d_in, const int* in_sizes, int n_in,
                              void* d_out, int out_size) {
    const float* x   = (const float*)d_in[0];
    const int*   nb1 = (const int*)  d_in[1];
    const int*   nb2 = (const int*)  d_in[2];
    const float* W1  = (const float*)d_in[3];
    const float* W2  = (const float*)d_in[4];
    const float* fcw = (const float*)d_in[5];
    const float* fcb = (const float*)d_in[6];
    float* out = (float*)d_out;

    cudaFuncSetAttribute(gemm_kernel, cudaFuncAttributeMaxDynamicSharedMemorySize, SMEM_TOTAL);

    prep_kernel<<<CONV_BLOCKS + (NCOL * DIM) / 1024, 256>>>(x, W1, W2);

    dim3 grid1(9, NPAD / BM);                              // (9, 392): +fcw converter
    dim3 grid2(8, NPAD / BM);                              // (8, 392)
    gemm_kernel<<<grid1, 256, SMEM_TOTAL>>>(0, fcw);       // layer 1 -> g_Ch (+fcw->fp16)
    combine1_kernel<<<NPAD / 4, 256>>>(nb1);               // -> g_Ah (fp16)
    gemm_kernel<<<grid2, 256, SMEM_TOTAL>>>(1, fcw);       // layer 2 -> g_Ch
    combine2_kernel<<<NN / 8, 512>>>(nb2, out);            // flat -> d_out, FC partials
    final_kernel<<<1, 256>>>(fcb, out + (size_t)(out_size - 2));
}

// round 17
// speedup vs baseline: 1.0401x; 1.0383x over previous
#include <cuda_runtime.h>
#include <cuda_fp16.h>
#include <cstdint>

#define NN 50000
#define NPAD 50176          // 392 * 128
#define DIM 512
#define NCOL 1024
#define BM 128
#define BN 128
#define BK 64               // fp16 per k-chunk = 128 bytes per row
#define CHUNKS 8            // DIM / BK
#define STAGES 3
#define STAGE_BYTES 32768   // A 16KB + B 16KB
#define SMEM_TOTAL (STAGES * STAGE_BYTES)

typedef unsigned long long ull;

// ---------------- static device scratch (no allocation) ----------------
// NOTE: __device__ globals are zero-initialized at module load; padded rows
// (i >= NN) of g_Ah are never written non-zero, so kernels skip them entirely.
__device__ __align__(16) __half g_Ah[(size_t)NPAD * DIM];    // 51 MB  fp16 A
__device__ __align__(16) __half g_B1p[NCOL * DIM];           // 1 MB  Bh layer1
__device__ __align__(16) __half g_B2p[NCOL * DIM];           // 1 MB  Bh layer2
__device__ __align__(16) __half g_Ch[(size_t)NPAD * NCOL];   // 102 MB  fp16 C
__device__ float g_part[2 * NN];

// ---------------- PTX helpers ----------------
__device__ __forceinline__ uint32_t smem_u32(const void* p) {
    uint32_t a;
    asm("{ .reg .u64 t; cvta.to.shared.u64 t, %1; cvt.u32.u64 %0, t; }" : "=r"(a) : "l"(p));
    return a;
}
#define CP16(dst, src) asm volatile("cp.async.cg.shared.global [%0], [%1], 16;" :: "r"(dst), "l"(src))
#define CP_COMMIT()    asm volatile("cp.async.commit_group;" ::: "memory")
#define CP_WAIT(n)     asm volatile("cp.async.wait_group %0;" :: "n"(n) : "memory")

#define LDSM_X4(r0, r1, r2, r3, a) \
    asm volatile("ldmatrix.sync.aligned.m8n8.x4.shared.b16 {%0,%1,%2,%3}, [%4];" \
        : "=r"(r0), "=r"(r1), "=r"(r2), "=r"(r3) : "r"(a))

#define MMA16816(c, a, b) \
    asm volatile("mma.sync.aligned.m16n8k16.row.col.f32.f16.f16.f32 " \
        "{%0,%1,%2,%3}, {%4,%5,%6,%7}, {%8,%9}, {%0,%1,%2,%3};" \
        : "+f"((c)[0]), "+f"((c)[1]), "+f"((c)[2]), "+f"((c)[3]) \
        : "r"((a)[0]), "r"((a)[1]), "r"((a)[2]), "r"((a)[3]), "r"((b)[0]), "r"((b)[1]))

__device__ __forceinline__ float2 h2f(uint32_t u) { return __half22float2(*(__half2*)&u); }

// ---------------- fused prep: convert x -> fp16 (blocks 0..NPAD/4-1),
//                  pack W1/W2 -> fp16 (blocks NPAD/4..NPAD/4+511) ----------------
#define CONV_BLOCKS (NPAD / 4)
__global__ void prep_kernel(const float* __restrict__ x,
                            const float* __restrict__ W1,
                            const float* __restrict__ W2) {
    int b = blockIdx.x;
    int tid = threadIdx.x;
    if (b < CONV_BLOCKS) {
        int i = b * 4 + (tid >> 6);
        if (i >= NN) return;                       // padded rows stay zero
        int j = (tid & 63) * 8;
        __half* row = g_Ah + (size_t)i * DIM;
        float4 a = *(const float4*)(x + (size_t)i * DIM + j);
        float4 c = *(const float4*)(x + (size_t)i * DIM + j + 4);
        __half h[8] = { __float2half_rn(a.x), __float2half_rn(a.y),
                        __float2half_rn(a.z), __float2half_rn(a.w),
                        __float2half_rn(c.x), __float2half_rn(c.y),
                        __float2half_rn(c.z), __float2half_rn(c.w) };
        *(uint4*)(row + j) = *(uint4*)h;
    } else {
        int e = ((b - CONV_BLOCKS) * 256 + tid) * 4;       // 4 consecutive elems, same n
        int n = e >> 9, k = e & 511;
        int src = (n < DIM) ? (n * NCOL + k) : ((n - DIM) * NCOL + DIM + k);
        float4 w1 = *(const float4*)(W1 + src);
        float4 w2 = *(const float4*)(W2 + src);
        __half h1[4] = { __float2half_rn(w1.x), __float2half_rn(w1.y),
                         __float2half_rn(w1.z), __float2half_rn(w1.w) };
        __half h2[4] = { __float2half_rn(w2.x), __float2half_rn(w2.y),
                         __float2half_rn(w2.z), __float2half_rn(w2.w) };
        *(ull*)(g_B1p + e) = *(ull*)h1;
        *(ull*)(g_B2p + e) = *(ull*)h2;
    }
}

// ---------------- fp16 HMMA GEMM: g_Ch[M,1024] = A[M,512] @ B^T ----------------
// CTA 128x128x64, warp tile 64x32, 3-stage cp.async pipeline, 2 CTAs/SM.
__global__ __launch_bounds__(256, 2) void gemm_kernel(int layer) {
    extern __shared__ __align__(1024) char smem[];
    const uint32_t sbase = smem_u32(smem);
    const int tid = threadIdx.x;
    const int wid = tid >> 5;
    const int lane = tid & 31;
    const int wm = wid & 1;           // 2 warps along M
    const int wn = wid >> 1;          // 4 warps along N
    const __half* __restrict__ Bp = layer ? g_B2p : g_B1p;
    const size_t mBase = (size_t)blockIdx.y * BM;
    const int nBase = blockIdx.x * BN;

    const char* gA0 = (const char*)g_Ah + mBase * (DIM * 2);
    const char* gB0 = (const char*)Bp + (size_t)nBase * (DIM * 2);

    auto load_chunk = [&](int kc, int s) {
        uint32_t sA = sbase + s * STAGE_BYTES;
        uint32_t sB = sA + 16384;
        const char* gA = gA0 + kc * 128;
        const char* gB = gB0 + kc * 128;
        #pragma unroll
        for (int i = 0; i < 4; i++) {
            int u = tid + i * 256;            // 0..1023
            int r = u >> 3, c = u & 7;
            uint32_t sw = (uint32_t)(r * 128 + (((c ^ (r & 7))) << 4));
            CP16(sA + sw, gA + (size_t)r * 1024 + c * 16);
            CP16(sB + sw, gB + (size_t)r * 1024 + c * 16);
        }
    };

    float acc[4][4][4];
    #pragma unroll
    for (int i = 0; i < 4; i++)
        #pragma unroll
        for (int j = 0; j < 4; j++)
            #pragma unroll
            for (int q = 0; q < 4; q++) acc[i][j][q] = 0.f;

    load_chunk(0, 0); CP_COMMIT();
    load_chunk(1, 1); CP_COMMIT();

    const int lrow = lane & 15;       // row within 16
    const int lhalf = lane >> 4;      // k-half

    #pragma unroll
    for (int kc = 0; kc < CHUNKS; kc++) {
        CP_WAIT(1);                   // chunk kc resident
        __syncthreads();

        uint32_t sA = sbase + (kc % STAGES) * STAGE_BYTES;
        uint32_t sB = sA + 16384;

        #pragma unroll
        for (int ks = 0; ks < 4; ks++) {
            uint32_t af[4][4], bf[4][2];
            #pragma unroll
            for (int am = 0; am < 4; am++) {
                int row = wm * 64 + am * 16 + lrow;
                int grp = ks * 2 + lhalf;
                uint32_t addr = sA + row * 128 + (((grp ^ (row & 7))) << 4);
                LDSM_X4(af[am][0], af[am][1], af[am][2], af[am][3], addr);
            }
            #pragma unroll
            for (int p = 0; p < 2; p++) {
                int row = wn * 32 + p * 16 + lrow;
                int grp = ks * 2 + lhalf;
                uint32_t addr = sB + row * 128 + (((grp ^ (row & 7))) << 4);
                uint32_t r0, r1, r2, r3;
                LDSM_X4(r0, r1, r2, r3, addr);
                bf[p * 2 + 0][0] = r0; bf[p * 2 + 0][1] = r2;
                bf[p * 2 + 1][0] = r1; bf[p * 2 + 1][1] = r3;
            }
            #pragma unroll
            for (int am = 0; am < 4; am++)
                #pragma unroll
                for (int bn = 0; bn < 4; bn++)
                    MMA16816(acc[am][bn], af[am], bf[bn]);
        }
        if (kc + 2 < CHUNKS) load_chunk(kc + 2, (kc + 2) % STAGES);
        CP_COMMIT();
    }

    // epilogue: fp16 store. c frag m16n8 -> (row = l>>2 [+8], col = (l&3)*2)
    const int crow = lane >> 2;
    const int ccol = (lane & 3) * 2;
    #pragma unroll
    for (int am = 0; am < 4; am++) {
        size_t r0 = mBase + wm * 64 + am * 16 + crow;
        #pragma unroll
        for (int bn = 0; bn < 4; bn++) {
            int c0 = nBase + wn * 32 + bn * 8 + ccol;
            __half2* p0 = (__half2*)(g_Ch + r0 * NCOL + c0);
            __half2* p1 = (__half2*)(g_Ch + (r0 + 8) * NCOL + c0);
            *p0 = __floats2half2_rn(acc[am][bn][0], acc[am][bn][1]);
            *p1 = __floats2half2_rn(acc[am][bn][2], acc[am][bn][3]);
        }
    }
}

// ---------------- layer-1 combine -> fp16: A <- relu(Y + 0.5*(Z0+Z1)) ----------------
// 4 rows per 256-thread block; 64 threads per row, 8 halves each (16B loads).
__global__ void combine1_kernel(const int* __restrict__ neighs) {
    int i = blockIdx.x * 4 + (threadIdx.x >> 6);
    if (i >= NN) return;                           // padded rows stay zero
    int j = (threadIdx.x & 63) * 8;
    __half* row = g_Ah + (size_t)i * DIM;
    int n0 = neighs[2 * i], n1 = neighs[2 * i + 1];
    uint4 ys = *(const uint4*)(g_Ch + (size_t)i  * NCOL + j);
    uint4 z0 = *(const uint4*)(g_Ch + (size_t)n0 * NCOL + DIM + j);
    uint4 z1 = *(const uint4*)(g_Ch + (size_t)n1 * NCOL + DIM + j);
    const uint32_t* yp = &ys.x;
    const uint32_t* p0 = &z0.x;
    const uint32_t* p1 = &z1.x;
    __half h[8];
    #pragma unroll
    for (int q = 0; q < 4; q++) {
        float2 s = h2f(yp[q]), a0 = h2f(p0[q]), a1 = h2f(p1[q]);
        h[q * 2 + 0] = __float2half_rn(fmaxf(fmaf(0.5f, a0.x + a1.x, s.x), 0.f));
        h[q * 2 + 1] = __float2half_rn(fmaxf(fmaf(0.5f, a0.y + a1.y, s.y), 0.f));
    }
    *(uint4*)(row + j) = *(uint4*)h;
}

// ---------------- layer-2 combine fused with FC-head partial dots ----------------
// 8 rows per 512-thread block; 2 warps per row.
__global__ void combine2_kernel(const int* __restrict__ neighs,
                                const float* __restrict__ fcw,
                                float* __restrict__ out) {
    int tid = threadIdx.x;
    int i = blockIdx.x * 8 + (tid >> 6);
    int j = (tid & 63) * 8;
    int n0 = neighs[2 * i], n1 = neighs[2 * i + 1];
    uint4 ys = *(const uint4*)(g_Ch + (size_t)i  * NCOL + j);
    uint4 z0 = *(const uint4*)(g_Ch + (size_t)n0 * NCOL + DIM + j);
    uint4 z1 = *(const uint4*)(g_Ch + (size_t)n1 * NCOL + DIM + j);
    const uint32_t* yp = &ys.x;
    const uint32_t* p0 = &z0.x;
    const uint32_t* p1 = &z1.x;
    size_t idx = (size_t)i * DIM + j;
    float o[8];
    #pragma unroll
    for (int q = 0; q < 4; q++) {
        float2 s = h2f(yp[q]), a0 = h2f(p0[q]), a1 = h2f(p1[q]);
        o[q * 2 + 0] = fmaxf(fmaf(0.5f, a0.x + a1.x, s.x), 0.f);
        o[q * 2 + 1] = fmaxf(fmaf(0.5f, a0.y + a1.y, s.y), 0.f);
    }
    *(float4*)(out + idx) = make_float4(o[0], o[1], o[2], o[3]);
    *(float4*)(out + idx + 4) = make_float4(o[4], o[5], o[6], o[7]);

    float p0s = 0.f, p1s = 0.f;
    #pragma unroll
    for (int half = 0; half < 2; half++) {
        float4 w0 = *(const float4*)(fcw + idx + half * 4);
        float4 w1 = *(const float4*)(fcw + (size_t)NN * DIM + idx + half * 4);
        const float* ov = o + half * 4;
        p0s += ov[0] * w0.x + ov[1] * w0.y + ov[2] * w0.z + ov[3] * w0.w;
        p1s += ov[0] * w1.x + ov[1] * w1.y + ov[2] * w1.z + ov[3] * w1.w;
    }

    // warp shuffle reduce (deterministic), then pair-combine the 2 warps per row
    #pragma unroll
    for (int st = 16; st > 0; st >>= 1) {
        p0s += __shfl_down_sync(0xFFFFFFFF, p0s, st);
        p1s += __shfl_down_sync(0xFFFFFFFF, p1s, st);
    }
    __shared__ float s0[16], s1[16];
    int w = tid >> 5;
    if ((tid & 31) == 0) { s0[w] = p0s; s1[w] = p1s; }
    __syncthreads();
    if ((tid & 63) == 0) {
        g_part[i]      = s0[w] + s0[w + 1];
        g_part[NN + i] = s1[w] + s1[w + 1];
    }
}

// ---------------- final: deterministic reduce + bias + log_softmax ----------------
__global__ void final_kernel(const float* __restrict__ fcb, float* __restrict__ out2) {
    __shared__ float s0[1024], s1[1024];
    int tid = threadIdx.x;
    float a = 0.f, b = 0.f;
    for (int i = tid; i < NN; i += 1024) { a += g_part[i]; b += g_part[NN + i]; }
    s0[tid] = a; s1[tid] = b;
    __syncthreads();
    #pragma unroll
    for (int st = 512; st > 0; st >>= 1) {
        if (tid < st) { s0[tid] += s0[tid + st]; s1[tid] += s1[tid + st]; }
        __syncthreads();
    }
    if (tid == 0) {
        float l0 = s0[0] + fcb[0];
        float l1 = s1[0] + fcb[1];
        float m = fmaxf(l0, l1);
        float lse = m + logf(expf(l0 - m) + expf(l1 - m));
        out2[0] = l0 - lse;
        out2[1] = l1 - lse;
    }
}

// ---------------- launch ----------------
extern "C" void kernel_launch(void* const* d_in, const int* in_sizes, int n_in,
                              void* d_out, int out_size) {
    const float* x   = (const float*)d_in[0];
    const int*   nb1 = (const int*)  d_in[1];
    const int*   nb2 = (const int*)  d_in[2];
    const float* W1  = (const float*)d_in[3];
    const float* W2  = (const float*)d_in[4];
    const float* fcw = (const float*)d_in[5];
    const float* fcb = (const float*)d_in[6];
    float* out = (float*)d_out;

    cudaFuncSetAttribute(gemm_kernel, cudaFuncAttributeMaxDynamicSharedMemorySize, SMEM_TOTAL);

    prep_kernel<<<CONV_BLOCKS + (NCOL * DIM) / 1024, 256>>>(x, W1, W2);

    dim3 grid(NCOL / BN, NPAD / BM);                       // (8, 392)
    gemm_kernel<<<grid, 256, SMEM_TOTAL>>>(0);             // layer 1 -> g_Ch
    combine1_kernel<<<NPAD / 4, 256>>>(nb1);               // -> g_Ah (fp16)
    gemm_kernel<<<grid, 256, SMEM_TOTAL>>>(1);             // layer 2 -> g_Ch
    combine2_kernel<<<NN / 8, 512>>>(nb2, fcw, out);       // flat -> d_out, FC partials
    final_kernel<<<1, 1024>>>(fcb, out + (size_t)(out_size - 2));
}